// round 13
// baseline (speedup 1.0000x reference)
#include <cuda_runtime.h>
#include <cuda_bf16.h>
#include <math.h>

// Problem constants
#define CB 2
#define CS 2048
#define CHID 1024
#define CH 8
#define CKV 4
#define CD 128
#define CBS (CB * CS)                 // 4096 rows
#define CSCALE 0.08838834764831845f   // 128^-0.5

// Scratch (allocation-free rule: __device__ globals)
__device__ float g_q[CBS * CH * CD];      // rope'd, tf32-RNA rounded
__device__ float g_k[CBS * CKV * CD];     // rope'd, tf32-RNA rounded
__device__ float g_v[CBS * CKV * CD];     // tf32-RNA rounded at qkv epilogue
__device__ float g_biasT[CH * CB * CS];   // dyn transposed: [h][b][s]

// bf16x3 packed operands: u32 = bf16 pair along K; hi and lo arrays.
__device__ unsigned g_hid_hi[CBS * 512], g_hid_lo[CBS * 512];   // [row][k2]
__device__ unsigned g_wq_hi[1024 * 512], g_wq_lo[1024 * 512];   // [col][k2]
__device__ unsigned g_wk_hi[512 * 512],  g_wk_lo[512 * 512];
__device__ unsigned g_wv_hi[512 * 512],  g_wv_lo[512 * 512];
__device__ unsigned g_wo_hi[1024 * 512], g_wo_lo[1024 * 512];
__device__ unsigned g_at_hi[CBS * 512],  g_at_lo[CBS * 512];    // attn out packed

__device__ __forceinline__ void cp16(unsigned dst, const void* src) {
    asm volatile("cp.async.cg.shared.global [%0], [%1], 16;\n" :: "r"(dst), "l"(src));
}

__device__ __forceinline__ unsigned f2tf32(float x) {
    unsigned r;
    asm("cvt.rna.tf32.f32 %0, %1;\n" : "=r"(r) : "f"(x));
    return r;
}
__device__ __forceinline__ float tf32r(float x) { return __uint_as_float(f2tf32(x)); }

__device__ __forceinline__ void mma_tf32(float* d, const unsigned* a, const unsigned* b) {
    asm volatile(
        "mma.sync.aligned.m16n8k8.row.col.f32.tf32.tf32.f32 "
        "{%0,%1,%2,%3}, {%4,%5,%6,%7}, {%8,%9}, {%0,%1,%2,%3};\n"
        : "+f"(d[0]), "+f"(d[1]), "+f"(d[2]), "+f"(d[3])
        : "r"(a[0]), "r"(a[1]), "r"(a[2]), "r"(a[3]), "r"(b[0]), "r"(b[1]));
}

__device__ __forceinline__ void mma_bf16(float* d, const unsigned* a, const unsigned* b) {
    asm volatile(
        "mma.sync.aligned.m16n8k16.row.col.f32.bf16.bf16.f32 "
        "{%0,%1,%2,%3}, {%4,%5,%6,%7}, {%8,%9}, {%0,%1,%2,%3};\n"
        : "+f"(d[0]), "+f"(d[1]), "+f"(d[2]), "+f"(d[3])
        : "r"(a[0]), "r"(a[1]), "r"(a[2]), "r"(a[3]), "r"(b[0]), "r"(b[1]));
}

// pack pair (x0 -> low16, x1 -> high16) into hi/lo bf16 residual split
__device__ __forceinline__ void bf16x3_pack(float x0, float x1, unsigned& hi, unsigned& lo) {
    const __nv_bfloat16 h0 = __float2bfloat16_rn(x0);
    const __nv_bfloat16 h1 = __float2bfloat16_rn(x1);
    const __nv_bfloat16 l0 = __float2bfloat16_rn(x0 - __bfloat162float(h0));
    const __nv_bfloat16 l1 = __float2bfloat16_rn(x1 - __bfloat162float(h1));
    __nv_bfloat162 H; H.x = h0; H.y = h1;
    __nv_bfloat162 L; L.x = l0; L.y = l1;
    hi = *(const unsigned*)&H;
    lo = *(const unsigned*)&L;
}

// ---------------------------------------------------------------------------
// Convert kernels (destinations resolved in device code only — GB300 ATS trap:
// __device__ symbols passed as host-side kernel args resolve to host shadows)
// ---------------------------------------------------------------------------
__global__ void k_cvtA(const float* __restrict__ hidden)
{
    const int idx = blockIdx.x * blockDim.x + threadIdx.x;   // over CBS*512
    if (idx >= CBS * 512) return;
    const float2 v = *(const float2*)(hidden + (size_t)idx * 2);
    bf16x3_pack(v.x, v.y, g_hid_hi[idx], g_hid_lo[idx]);
}

// One launch converts all 4 weights: blockIdx.z selects the job.
__global__ void __launch_bounds__(256) k_cvtW_all(
    const float* __restrict__ Wq, const float* __restrict__ Wk,
    const float* __restrict__ Wv, const float* __restrict__ Wo)
{
    const int which = blockIdx.z;
    const float* src; unsigned* dhi; unsigned* dlo; int N;
    switch (which) {
        case 0:  src = Wq; dhi = g_wq_hi; dlo = g_wq_lo; N = 1024; break;
        case 1:  src = Wk; dhi = g_wk_hi; dlo = g_wk_lo; N = 512;  break;
        case 2:  src = Wv; dhi = g_wv_hi; dlo = g_wv_lo; N = 512;  break;
        default: src = Wo; dhi = g_wo_hi; dlo = g_wo_lo; N = 1024; break;
    }
    const int n0 = blockIdx.y * 32;
    if (n0 >= N) return;
    __shared__ float smW[64][33];
    const int tid = threadIdx.x;
    const int k0 = blockIdx.x * 64;
#pragma unroll
    for (int i = 0; i < 8; ++i) {
        const int idx = tid + i * 256;
        const int r = idx >> 5, c = idx & 31;
        smW[r][c] = src[(size_t)(k0 + r) * N + n0 + c];
    }
    __syncthreads();
    const int n = tid >> 3;
#pragma unroll
    for (int j = 0; j < 4; ++j) {
        const int k2 = (tid & 7) + j * 8;
        unsigned hi, lo;
        bf16x3_pack(smW[2 * k2][n], smW[2 * k2 + 1][n], hi, lo);
        const size_t o = (size_t)(n0 + n) * 512 + (k0 >> 1) + k2;
        dhi[o] = hi; dlo[o] = lo;
    }
}

// ===========================================================================
// bf16x3 tensor-core GEMM: C[128,128] = A[128,1024] @ B[1024,128]
// (unchanged from round 12; at the legacy-HMMA rate floor)
// ===========================================================================
#define PSTRIDE 20
#define STG_U32 (128 * PSTRIDE)       // 2560 per array per stage
#define SA_H 0
#define SA_L (2 * STG_U32)            // 5120
#define SB_H (4 * STG_U32)            // 10240
#define SB_L (6 * STG_U32)            // 15360
#define GEMM_SMEM_BYTES (8 * STG_U32 * 4)   // 81920

__device__ __forceinline__ void gemm128_bf16x3(
    const unsigned* __restrict__ Ahi, const unsigned* __restrict__ Alo, int arow0,
    const unsigned* __restrict__ Bhi, const unsigned* __restrict__ Blo, int bcol0,
    float* __restrict__ C, int ldc, bool roundC)
{
    extern __shared__ unsigned smu[];
    const unsigned smBase = (unsigned)__cvta_generic_to_shared(smu);

    const int tid = threadIdx.x;
    const int w = tid >> 5, lane = tid & 31;
    const int g = lane >> 2, t = lane & 3;
    const int rb = (w >> 2) * 64;
    const int cb = (w & 3) * 32;

    float acc[4][4][4];
#pragma unroll
    for (int mt = 0; mt < 4; ++mt)
#pragma unroll
        for (int nt = 0; nt < 4; ++nt)
#pragma unroll
            for (int r = 0; r < 4; ++r) acc[mt][nt][r] = 0.f;

    const unsigned* srcs[4] = { Ahi, Alo, Bhi, Blo };
    const int base0[4] = { arow0, arow0, bcol0, bcol0 };
    const int dstb[4] = { SA_H, SA_L, SB_H, SB_L };

    auto issue = [&](int k0, int st) {
        const int k2_0 = k0 >> 1;
#pragma unroll
        for (int i = 0; i < 8; ++i) {
            const int idx = tid + i * 256;
            const int sub = idx >> 9;
            const int j = idx & 511;
            const int r = j >> 2, c4 = (j & 3) << 2;
            cp16(smBase + (unsigned)((dstb[sub] + st * STG_U32 + r * PSTRIDE + c4) << 2),
                 srcs[sub] + (size_t)(base0[sub] + r) * 512 + k2_0 + c4);
        }
        asm volatile("cp.async.commit_group;\n");
    };

    issue(0, 0);
    int st = 0;
    for (int k0 = 0; k0 < 1024; k0 += 32) {
        asm volatile("cp.async.wait_group 0;\n");
        __syncthreads();
        if (k0 + 32 < 1024) issue(k0 + 32, st ^ 1);
        const unsigned* AH = smu + SA_H + st * STG_U32;
        const unsigned* AL = smu + SA_L + st * STG_U32;
        const unsigned* BH = smu + SB_H + st * STG_U32;
        const unsigned* BL = smu + SB_L + st * STG_U32;
#pragma unroll
        for (int ks = 0; ks < 2; ++ks) {
            const int kk2 = ks * 8;
            unsigned ah[4][4], al[4][4], bh[4][2], bl[4][2];
#pragma unroll
            for (int mt = 0; mt < 4; ++mt) {
                const int ro = (rb + mt * 16 + g) * PSTRIDE + kk2;
                ah[mt][0] = AH[ro + t];
                ah[mt][1] = AH[ro + 8 * PSTRIDE + t];
                ah[mt][2] = AH[ro + t + 4];
                ah[mt][3] = AH[ro + 8 * PSTRIDE + t + 4];
                al[mt][0] = AL[ro + t];
                al[mt][1] = AL[ro + 8 * PSTRIDE + t];
                al[mt][2] = AL[ro + t + 4];
                al[mt][3] = AL[ro + 8 * PSTRIDE + t + 4];
            }
#pragma unroll
            for (int nt = 0; nt < 4; ++nt) {
                const int co = (cb + nt * 8 + g) * PSTRIDE + kk2;
                bh[nt][0] = BH[co + t];
                bh[nt][1] = BH[co + t + 4];
                bl[nt][0] = BL[co + t];
                bl[nt][1] = BL[co + t + 4];
            }
#pragma unroll
            for (int mt = 0; mt < 4; ++mt)
#pragma unroll
                for (int nt = 0; nt < 4; ++nt) {
                    mma_bf16(acc[mt][nt], al[mt], bh[nt]);
                    mma_bf16(acc[mt][nt], ah[mt], bl[nt]);
                    mma_bf16(acc[mt][nt], ah[mt], bh[nt]);
                }
        }
        st ^= 1;
    }

#pragma unroll
    for (int mt = 0; mt < 4; ++mt)
#pragma unroll
        for (int nt = 0; nt < 4; ++nt) {
            const int r0 = rb + mt * 16 + g;
            const int c0 = cb + nt * 8 + 2 * t;
            float v0 = acc[mt][nt][0], v1 = acc[mt][nt][1];
            float v2 = acc[mt][nt][2], v3 = acc[mt][nt][3];
            if (roundC) { v0 = tf32r(v0); v1 = tf32r(v1); v2 = tf32r(v2); v3 = tf32r(v3); }
            *(float2*)(C + (size_t)r0 * ldc + c0)       = make_float2(v0, v1);
            *(float2*)(C + (size_t)(r0 + 8) * ldc + c0) = make_float2(v2, v3);
        }
}

// Kernel 1: fused QKV projection; V output rounded to tf32 (PV exactness)
__global__ void __launch_bounds__(256, 2) k_qkv_tc()
{
    const int n0 = blockIdx.x * 128;
    const int m0 = blockIdx.y * 128;
    if (n0 < 1024)
        gemm128_bf16x3(g_hid_hi, g_hid_lo, m0, g_wq_hi, g_wq_lo, n0,
                       g_q + (size_t)m0 * 1024 + n0, 1024, false);
    else if (n0 < 1536)
        gemm128_bf16x3(g_hid_hi, g_hid_lo, m0, g_wk_hi, g_wk_lo, n0 - 1024,
                       g_k + (size_t)m0 * 512 + (n0 - 1024), 512, false);
    else
        gemm128_bf16x3(g_hid_hi, g_hid_lo, m0, g_wv_hi, g_wv_lo, n0 - 1536,
                       g_v + (size_t)m0 * 512 + (n0 - 1536), 512, true);
}

// Kernel 5: output projection from packed attention output
__global__ void __launch_bounds__(256, 2) k_out_tc(float* __restrict__ out)
{
    const int n0 = blockIdx.x * 128;
    const int m0 = blockIdx.y * 128;
    gemm128_bf16x3(g_at_hi, g_at_lo, m0, g_wo_hi, g_wo_lo, n0,
                   out + (size_t)m0 * 1024 + n0, 1024, false);
}

// ---------------------------------------------------------------------------
// Kernel 2: RoPE on q and k -- writes tf32-RNA-rounded values (QK exactness)
// ---------------------------------------------------------------------------
__global__ void k_rope(const float* __restrict__ cosb, const float* __restrict__ sinb)
{
    const int t = blockIdx.x * blockDim.x + threadIdx.x;
    const int total = CBS * 12 * 64;
    if (t >= total) return;
    const int d = t & 63;
    const int head = (t >> 6) % 12;
    const int row = t / (12 * 64);
    const int s = row & (CS - 1);
    const float c1  = cosb[s * CD + d];
    const float sn1 = sinb[s * CD + d];
    const float c2  = cosb[s * CD + d + 64];
    const float sn2 = sinb[s * CD + d + 64];
    float* p;
    if (head < CH) p = g_q + (size_t)row * (CH * CD) + head * CD;
    else           p = g_k + (size_t)row * (CKV * CD) + (head - CH) * CD;
    const float x1 = p[d], x2 = p[d + 64];
    p[d]      = tf32r(x1 * c1 - x2 * sn1);
    p[d + 64] = tf32r(x2 * c2 + x1 * sn2);
}

// ---------------------------------------------------------------------------
// Kernel 3: dt = v_flat @ Wdt ; dyn = exp(A * softplus(dt)) -> g_biasT [h][b][s]
// ---------------------------------------------------------------------------
__global__ void __launch_bounds__(256) k_biask(
    const float* __restrict__ Wdt, const float* __restrict__ Aw)
{
    __shared__ float sW[512 * 8];
    for (int i = threadIdx.x; i < 512 * 8; i += 256) sW[i] = Wdt[i];
    __syncthreads();
    const int warp = threadIdx.x >> 5;
    const int lane = threadIdx.x & 31;
    const int row = blockIdx.x * 8 + warp;
    const float* vrow = g_v + (size_t)row * 512;
    float acc[8];
#pragma unroll
    for (int h = 0; h < 8; ++h) acc[h] = 0.f;
    for (int j = lane; j < 512; j += 32) {
        const float vv = vrow[j];
#pragma unroll
        for (int h = 0; h < 8; ++h) acc[h] = fmaf(vv, sW[j * 8 + h], acc[h]);
    }
#pragma unroll
    for (int off = 16; off > 0; off >>= 1)
#pragma unroll
        for (int h = 0; h < 8; ++h)
            acc[h] += __shfl_xor_sync(0xffffffffu, acc[h], off);
    if (lane < 8) {
        const float dt = acc[lane];
        const float sp = (dt > 20.f) ? dt : log1pf(expf(dt));
        const int b = row >> 11;
        const int s = row & (CS - 1);
        g_biasT[(size_t)(lane * CB + b) * CS + s] = expf(Aw[lane] * sp);
    }
}

// ===========================================================================
// Kernel 4: causal flash attention, tf32 mma.
// BALANCED SCHEDULE: 128 CTAs; CTA id=(bh,j) processes qt=15-j then qt=j.
// work(qt)=2qt+2 units; (15-j)+(j) pair always sums to 34 units -> one wave,
// identical load per CTA (vs ~48-unit makespan with the 256-CTA grid).
// ===========================================================================
#define KSTR 132
#define VSTR 136
#define PST 68
#define AT_KS 0
#define AT_VS (2 * 64 * KSTR)
#define AT_PS (AT_VS + 2 * 64 * VSTR)
#define AT_BIAS (AT_PS + 128 * PST)
#define ATTN_TC_FLOATS (AT_BIAS + 2 * 64)
#define ATTN_TC_BYTES (ATTN_TC_FLOATS * 4)

__global__ void __launch_bounds__(256, 1) k_attn_tc()
{
    extern __shared__ float sm[];
    float* Ks = sm + AT_KS;
    float* Vs = sm + AT_VS;
    float* Ps = sm + AT_PS;
    float* bias_s = sm + AT_BIAS;
    const unsigned smBase = (unsigned)__cvta_generic_to_shared(sm);

    const int tid = threadIdx.x;
    const int w = tid >> 5, lane = tid & 31;
    const int g = lane >> 2, t = lane & 3;
    const int id = blockIdx.x;          // 0..127
    const int bh = id >> 3;
    const int b = bh >> 3;
    const int h = bh & 7;
    const int kvh = h >> 1;
    const int jp = id & 7;              // pair index
    const int qw = w * 16;

    for (int item = 0; item < 2; ++item) {
        const int qt = item ? jp : (15 - jp);   // heavy tile first
        const int q0 = qt * 128;
        const int qg0 = q0 + qw + g;
        const int qg1 = qg0 + 8;

        unsigned aq[16][4];
        {
            const float* qp = g_q + (size_t)(b * CS + qg0) * 1024 + h * 128;
#pragma unroll
            for (int kf = 0; kf < 16; ++kf) {
                aq[kf][0] = __float_as_uint(qp[kf * 8 + t]);
                aq[kf][1] = __float_as_uint(qp[8 * 1024 + kf * 8 + t]);
                aq[kf][2] = __float_as_uint(qp[kf * 8 + t + 4]);
                aq[kf][3] = __float_as_uint(qp[8 * 1024 + kf * 8 + t + 4]);
            }
        }

        float O[16][4];
#pragma unroll
        for (int nt = 0; nt < 16; ++nt)
#pragma unroll
            for (int r = 0; r < 4; ++r) O[nt][r] = 0.f;
        float m0 = -1e30f, m1 = -1e30f, l0 = 0.f, l1 = 0.f;

        const int nkt = 2 * qt + 2;

        auto issue = [&](int kt, int st) {
            const int kbase = kt * 64;
#pragma unroll
            for (int i = 0; i < 8; ++i) {
                const int idx = tid + i * 256;
                const int c = idx >> 5, dc = (idx & 31) << 2;
                const size_t grow = (size_t)(b * CS + kbase + c) * 512 + kvh * 128 + dc;
                cp16(smBase + (unsigned)((AT_KS + st * 64 * KSTR + c * KSTR + dc) << 2), g_k + grow);
                cp16(smBase + (unsigned)((AT_VS + st * 64 * VSTR + c * VSTR + dc) << 2), g_v + grow);
            }
            if (tid < 16)
                cp16(smBase + (unsigned)((AT_BIAS + st * 64 + tid * 4) << 2),
                     g_biasT + (size_t)(h * CB + b) * CS + kbase + tid * 4);
            asm volatile("cp.async.commit_group;\n");
        };

        issue(0, 0);
        int st = 0;
        for (int kt = 0; kt < nkt; ++kt) {
            const int kbase = kt * 64;
            asm volatile("cp.async.wait_group 0;\n");
            __syncthreads();
            if (kt + 1 < nkt) issue(kt + 1, st ^ 1);

            const float* KsS = Ks + st * 64 * KSTR;
            const float* VsS = Vs + st * 64 * VSTR;
            const float* biasS = bias_s + st * 64;

            float sacc[8][4];
#pragma unroll
            for (int nt = 0; nt < 8; ++nt)
#pragma unroll
                for (int r = 0; r < 4; ++r) sacc[nt][r] = 0.f;
#pragma unroll
            for (int kf = 0; kf < 16; ++kf) {
#pragma unroll
                for (int nt = 0; nt < 8; ++nt) {
                    unsigned bf[2];
                    const float* kp = KsS + (nt * 8 + g) * KSTR + kf * 8 + t;
                    bf[0] = __float_as_uint(kp[0]);
                    bf[1] = __float_as_uint(kp[4]);
                    mma_tf32(sacc[nt], aq[kf], bf);
                }
            }

            float mx0 = -1e30f, mx1 = -1e30f;
#pragma unroll
            for (int nt = 0; nt < 8; ++nt) {
                const int kg = kbase + nt * 8 + 2 * t;
                const float b0 = biasS[nt * 8 + 2 * t];
                const float b1 = biasS[nt * 8 + 2 * t + 1];
                sacc[nt][0] = (kg     <= qg0) ? fmaf(sacc[nt][0], CSCALE, b0) : -1e30f;
                sacc[nt][1] = (kg + 1 <= qg0) ? fmaf(sacc[nt][1], CSCALE, b1) : -1e30f;
                sacc[nt][2] = (kg     <= qg1) ? fmaf(sacc[nt][2], CSCALE, b0) : -1e30f;
                sacc[nt][3] = (kg + 1 <= qg1) ? fmaf(sacc[nt][3], CSCALE, b1) : -1e30f;
                mx0 = fmaxf(mx0, fmaxf(sacc[nt][0], sacc[nt][1]));
                mx1 = fmaxf(mx1, fmaxf(sacc[nt][2], sacc[nt][3]));
            }
            mx0 = fmaxf(mx0, __shfl_xor_sync(0xffffffffu, mx0, 1));
            mx0 = fmaxf(mx0, __shfl_xor_sync(0xffffffffu, mx0, 2));
            mx1 = fmaxf(mx1, __shfl_xor_sync(0xffffffffu, mx1, 1));
            mx1 = fmaxf(mx1, __shfl_xor_sync(0xffffffffu, mx1, 2));

            const float mn0 = fmaxf(m0, mx0);
            const float mn1 = fmaxf(m1, mx1);
            const float alpha0 = __expf(m0 - mn0);
            const float alpha1 = __expf(m1 - mn1);
            float sum0 = 0.f, sum1 = 0.f;
#pragma unroll
            for (int nt = 0; nt < 8; ++nt) {
                const float p0 = tf32r(__expf(sacc[nt][0] - mn0));
                const float p1 = tf32r(__expf(sacc[nt][1] - mn0));
                const float p2 = tf32r(__expf(sacc[nt][2] - mn1));
                const float p3 = tf32r(__expf(sacc[nt][3] - mn1));
                sum0 += p0 + p1;
                sum1 += p2 + p3;
                *(float2*)&Ps[(qw + g) * PST + nt * 8 + 2 * t]     = make_float2(p0, p1);
                *(float2*)&Ps[(qw + g + 8) * PST + nt * 8 + 2 * t] = make_float2(p2, p3);
            }
            sum0 += __shfl_xor_sync(0xffffffffu, sum0, 1);
            sum0 += __shfl_xor_sync(0xffffffffu, sum0, 2);
            sum1 += __shfl_xor_sync(0xffffffffu, sum1, 1);
            sum1 += __shfl_xor_sync(0xffffffffu, sum1, 2);
            l0 = l0 * alpha0 + sum0;  m0 = mn0;
            l1 = l1 * alpha1 + sum1;  m1 = mn1;

#pragma unroll
            for (int nt = 0; nt < 16; ++nt) {
                O[nt][0] *= alpha0; O[nt][1] *= alpha0;
                O[nt][2] *= alpha1; O[nt][3] *= alpha1;
            }

            __syncwarp();
#pragma unroll
            for (int kf = 0; kf < 8; ++kf) {
                unsigned ap[4];
                const float* pp = Ps + (qw + g) * PST + kf * 8 + t;
                ap[0] = __float_as_uint(pp[0]);
                ap[1] = __float_as_uint(pp[8 * PST]);
                ap[2] = __float_as_uint(pp[4]);
                ap[3] = __float_as_uint(pp[8 * PST + 4]);
#pragma unroll
                for (int nt = 0; nt < 16; ++nt) {
                    unsigned bf[2];
                    const float* vp = VsS + (kf * 8 + t) * VSTR + nt * 8 + g;
                    bf[0] = __float_as_uint(vp[0]);
                    bf[1] = __float_as_uint(vp[4 * VSTR]);
                    mma_tf32(O[nt], ap, bf);
                }
            }
            __syncthreads();
            st ^= 1;
        }

        // epilogue: normalize and pack to bf16x3 operand layout for k_out.
        const float inv0 = 1.f / l0;
        const float inv1 = 1.f / l1;
        const size_t r0 = (size_t)(b * CS + qg0) * 512 + h * 64;
        const size_t r1 = (size_t)(b * CS + qg1) * 512 + h * 64;
#pragma unroll
        for (int nt = 0; nt < 16; ++nt) {
            unsigned hi, lo;
            bf16x3_pack(O[nt][0] * inv0, O[nt][1] * inv0, hi, lo);
            g_at_hi[r0 + nt * 4 + t] = hi;
            g_at_lo[r0 + nt * 4 + t] = lo;
            bf16x3_pack(O[nt][2] * inv1, O[nt][3] * inv1, hi, lo);
            g_at_hi[r1 + nt * 4 + t] = hi;
            g_at_lo[r1 + nt * 4 + t] = lo;
        }
        __syncthreads();   // smem safe for next item
    }
}

// ---------------------------------------------------------------------------
extern "C" void kernel_launch(void* const* d_in, const int* in_sizes, int n_in,
                              void* d_out, int out_size)
{
    const float* hidden = (const float*)d_in[0];
    const float* Wq     = (const float*)d_in[1];
    const float* Wk     = (const float*)d_in[2];
    const float* Wv     = (const float*)d_in[3];
    const float* Wdt    = (const float*)d_in[4];
    const float* Aw     = (const float*)d_in[5];
    const float* Wo     = (const float*)d_in[6];
    const float* cosb   = (const float*)d_in[7];
    const float* sinb   = (const float*)d_in[8];
    float* out = (float*)d_out;

    cudaFuncSetAttribute(k_qkv_tc,  cudaFuncAttributeMaxDynamicSharedMemorySize, GEMM_SMEM_BYTES);
    cudaFuncSetAttribute(k_out_tc,  cudaFuncAttributeMaxDynamicSharedMemorySize, GEMM_SMEM_BYTES);
    cudaFuncSetAttribute(k_attn_tc, cudaFuncAttributeMaxDynamicSharedMemorySize, ATTN_TC_BYTES);

    // one-time packs (2 launches; destinations resolved inside device code)
    k_cvtA<<<(CBS * 512 + 255) / 256, 256>>>(hidden);
    k_cvtW_all<<<dim3(16, 32, 4), 256>>>(Wq, Wk, Wv, Wo);

    k_qkv_tc<<<dim3(16, 32), 256, GEMM_SMEM_BYTES>>>();
    k_rope<<<(CBS * 12 * 64 + 255) / 256, 256>>>(cosb, sinb);
    k_biask<<<CBS / 8, 256>>>(Wdt, Aw);
    k_attn_tc<<<dim3(128), 256, ATTN_TC_BYTES>>>();
    k_out_tc<<<dim3(8, 32), 256, GEMM_SMEM_BYTES>>>(out);
}

// round 14
// speedup vs baseline: 1.0375x; 1.0375x over previous
#include <cuda_runtime.h>
#include <cuda_bf16.h>
#include <math.h>

// Problem constants
#define CB 2
#define CS 2048
#define CHID 1024
#define CH 8
#define CKV 4
#define CD 128
#define CBS (CB * CS)                 // 4096 rows
#define CSCALE 0.08838834764831845f   // 128^-0.5

// Scratch (allocation-free rule: __device__ globals)
__device__ float g_q[CBS * CH * CD];      // raw fp32 (rope+round fused into attn)
__device__ float g_k[CBS * CKV * CD];     // rope'd, tf32-RNA rounded
__device__ float g_v[CBS * CKV * CD];     // tf32-RNA rounded at qkv epilogue
__device__ float g_biasT[CH * CB * CS];   // dyn transposed: [h][b][s]

// bf16x3 packed operands: u32 = bf16 pair along K; hi and lo arrays.
__device__ unsigned g_hid_hi[CBS * 512], g_hid_lo[CBS * 512];   // [row][k2]
__device__ unsigned g_wq_hi[1024 * 512], g_wq_lo[1024 * 512];   // [col][k2]
__device__ unsigned g_wk_hi[512 * 512],  g_wk_lo[512 * 512];
__device__ unsigned g_wv_hi[512 * 512],  g_wv_lo[512 * 512];
__device__ unsigned g_wo_hi[1024 * 512], g_wo_lo[1024 * 512];
__device__ unsigned g_at_hi[CBS * 512],  g_at_lo[CBS * 512];    // attn out packed

__device__ __forceinline__ void cp16(unsigned dst, const void* src) {
    asm volatile("cp.async.cg.shared.global [%0], [%1], 16;\n" :: "r"(dst), "l"(src));
}

__device__ __forceinline__ unsigned f2tf32(float x) {
    unsigned r;
    asm("cvt.rna.tf32.f32 %0, %1;\n" : "=r"(r) : "f"(x));
    return r;
}
__device__ __forceinline__ float tf32r(float x) { return __uint_as_float(f2tf32(x)); }

__device__ __forceinline__ void mma_tf32(float* d, const unsigned* a, const unsigned* b) {
    asm volatile(
        "mma.sync.aligned.m16n8k8.row.col.f32.tf32.tf32.f32 "
        "{%0,%1,%2,%3}, {%4,%5,%6,%7}, {%8,%9}, {%0,%1,%2,%3};\n"
        : "+f"(d[0]), "+f"(d[1]), "+f"(d[2]), "+f"(d[3])
        : "r"(a[0]), "r"(a[1]), "r"(a[2]), "r"(a[3]), "r"(b[0]), "r"(b[1]));
}

__device__ __forceinline__ void mma_bf16(float* d, const unsigned* a, const unsigned* b) {
    asm volatile(
        "mma.sync.aligned.m16n8k16.row.col.f32.bf16.bf16.f32 "
        "{%0,%1,%2,%3}, {%4,%5,%6,%7}, {%8,%9}, {%0,%1,%2,%3};\n"
        : "+f"(d[0]), "+f"(d[1]), "+f"(d[2]), "+f"(d[3])
        : "r"(a[0]), "r"(a[1]), "r"(a[2]), "r"(a[3]), "r"(b[0]), "r"(b[1]));
}

// pack pair (x0 -> low16, x1 -> high16) into hi/lo bf16 residual split
__device__ __forceinline__ void bf16x3_pack(float x0, float x1, unsigned& hi, unsigned& lo) {
    const __nv_bfloat16 h0 = __float2bfloat16_rn(x0);
    const __nv_bfloat16 h1 = __float2bfloat16_rn(x1);
    const __nv_bfloat16 l0 = __float2bfloat16_rn(x0 - __bfloat162float(h0));
    const __nv_bfloat16 l1 = __float2bfloat16_rn(x1 - __bfloat162float(h1));
    __nv_bfloat162 H; H.x = h0; H.y = h1;
    __nv_bfloat162 L; L.x = l0; L.y = l1;
    hi = *(const unsigned*)&H;
    lo = *(const unsigned*)&L;
}

// ---------------------------------------------------------------------------
// Convert kernels (destinations resolved in device code only — GB300 ATS trap:
// __device__ symbols passed as host-side kernel args resolve to host shadows)
// ---------------------------------------------------------------------------
__global__ void k_cvtA(const float* __restrict__ hidden)
{
    const int idx = blockIdx.x * blockDim.x + threadIdx.x;   // over CBS*512
    if (idx >= CBS * 512) return;
    const float2 v = *(const float2*)(hidden + (size_t)idx * 2);
    bf16x3_pack(v.x, v.y, g_hid_hi[idx], g_hid_lo[idx]);
}

// One launch converts all 4 weights: blockIdx.z selects the job.
__global__ void __launch_bounds__(256) k_cvtW_all(
    const float* __restrict__ Wq, const float* __restrict__ Wk,
    const float* __restrict__ Wv, const float* __restrict__ Wo)
{
    const int which = blockIdx.z;
    const float* src; unsigned* dhi; unsigned* dlo; int N;
    switch (which) {
        case 0:  src = Wq; dhi = g_wq_hi; dlo = g_wq_lo; N = 1024; break;
        case 1:  src = Wk; dhi = g_wk_hi; dlo = g_wk_lo; N = 512;  break;
        case 2:  src = Wv; dhi = g_wv_hi; dlo = g_wv_lo; N = 512;  break;
        default: src = Wo; dhi = g_wo_hi; dlo = g_wo_lo; N = 1024; break;
    }
    const int n0 = blockIdx.y * 32;
    if (n0 >= N) return;
    __shared__ float smW[64][33];
    const int tid = threadIdx.x;
    const int k0 = blockIdx.x * 64;
#pragma unroll
    for (int i = 0; i < 8; ++i) {
        const int idx = tid + i * 256;
        const int r = idx >> 5, c = idx & 31;
        smW[r][c] = src[(size_t)(k0 + r) * N + n0 + c];
    }
    __syncthreads();
    const int n = tid >> 3;
#pragma unroll
    for (int j = 0; j < 4; ++j) {
        const int k2 = (tid & 7) + j * 8;
        unsigned hi, lo;
        bf16x3_pack(smW[2 * k2][n], smW[2 * k2 + 1][n], hi, lo);
        const size_t o = (size_t)(n0 + n) * 512 + (k0 >> 1) + k2;
        dhi[o] = hi; dlo[o] = lo;
    }
}

// ===========================================================================
// bf16x3 tensor-core GEMM (unchanged; at the legacy-HMMA rate floor)
// ===========================================================================
#define PSTRIDE 20
#define STG_U32 (128 * PSTRIDE)       // 2560 per array per stage
#define SA_H 0
#define SA_L (2 * STG_U32)            // 5120
#define SB_H (4 * STG_U32)            // 10240
#define SB_L (6 * STG_U32)            // 15360
#define GEMM_SMEM_BYTES (8 * STG_U32 * 4)   // 81920

__device__ __forceinline__ void gemm128_bf16x3(
    const unsigned* __restrict__ Ahi, const unsigned* __restrict__ Alo, int arow0,
    const unsigned* __restrict__ Bhi, const unsigned* __restrict__ Blo, int bcol0,
    float* __restrict__ C, int ldc, bool roundC)
{
    extern __shared__ unsigned smu[];
    const unsigned smBase = (unsigned)__cvta_generic_to_shared(smu);

    const int tid = threadIdx.x;
    const int w = tid >> 5, lane = tid & 31;
    const int g = lane >> 2, t = lane & 3;
    const int rb = (w >> 2) * 64;
    const int cb = (w & 3) * 32;

    float acc[4][4][4];
#pragma unroll
    for (int mt = 0; mt < 4; ++mt)
#pragma unroll
        for (int nt = 0; nt < 4; ++nt)
#pragma unroll
            for (int r = 0; r < 4; ++r) acc[mt][nt][r] = 0.f;

    const unsigned* srcs[4] = { Ahi, Alo, Bhi, Blo };
    const int base0[4] = { arow0, arow0, bcol0, bcol0 };
    const int dstb[4] = { SA_H, SA_L, SB_H, SB_L };

    auto issue = [&](int k0, int st) {
        const int k2_0 = k0 >> 1;
#pragma unroll
        for (int i = 0; i < 8; ++i) {
            const int idx = tid + i * 256;
            const int sub = idx >> 9;
            const int j = idx & 511;
            const int r = j >> 2, c4 = (j & 3) << 2;
            cp16(smBase + (unsigned)((dstb[sub] + st * STG_U32 + r * PSTRIDE + c4) << 2),
                 srcs[sub] + (size_t)(base0[sub] + r) * 512 + k2_0 + c4);
        }
        asm volatile("cp.async.commit_group;\n");
    };

    issue(0, 0);
    int st = 0;
    for (int k0 = 0; k0 < 1024; k0 += 32) {
        asm volatile("cp.async.wait_group 0;\n");
        __syncthreads();
        if (k0 + 32 < 1024) issue(k0 + 32, st ^ 1);
        const unsigned* AH = smu + SA_H + st * STG_U32;
        const unsigned* AL = smu + SA_L + st * STG_U32;
        const unsigned* BH = smu + SB_H + st * STG_U32;
        const unsigned* BL = smu + SB_L + st * STG_U32;
#pragma unroll
        for (int ks = 0; ks < 2; ++ks) {
            const int kk2 = ks * 8;
            unsigned ah[4][4], al[4][4], bh[4][2], bl[4][2];
#pragma unroll
            for (int mt = 0; mt < 4; ++mt) {
                const int ro = (rb + mt * 16 + g) * PSTRIDE + kk2;
                ah[mt][0] = AH[ro + t];
                ah[mt][1] = AH[ro + 8 * PSTRIDE + t];
                ah[mt][2] = AH[ro + t + 4];
                ah[mt][3] = AH[ro + 8 * PSTRIDE + t + 4];
                al[mt][0] = AL[ro + t];
                al[mt][1] = AL[ro + 8 * PSTRIDE + t];
                al[mt][2] = AL[ro + t + 4];
                al[mt][3] = AL[ro + 8 * PSTRIDE + t + 4];
            }
#pragma unroll
            for (int nt = 0; nt < 4; ++nt) {
                const int co = (cb + nt * 8 + g) * PSTRIDE + kk2;
                bh[nt][0] = BH[co + t];
                bh[nt][1] = BH[co + t + 4];
                bl[nt][0] = BL[co + t];
                bl[nt][1] = BL[co + t + 4];
            }
#pragma unroll
            for (int mt = 0; mt < 4; ++mt)
#pragma unroll
                for (int nt = 0; nt < 4; ++nt) {
                    mma_bf16(acc[mt][nt], al[mt], bh[nt]);
                    mma_bf16(acc[mt][nt], ah[mt], bl[nt]);
                    mma_bf16(acc[mt][nt], ah[mt], bh[nt]);
                }
        }
        st ^= 1;
    }

#pragma unroll
    for (int mt = 0; mt < 4; ++mt)
#pragma unroll
        for (int nt = 0; nt < 4; ++nt) {
            const int r0 = rb + mt * 16 + g;
            const int c0 = cb + nt * 8 + 2 * t;
            float v0 = acc[mt][nt][0], v1 = acc[mt][nt][1];
            float v2 = acc[mt][nt][2], v3 = acc[mt][nt][3];
            if (roundC) { v0 = tf32r(v0); v1 = tf32r(v1); v2 = tf32r(v2); v3 = tf32r(v3); }
            *(float2*)(C + (size_t)r0 * ldc + c0)       = make_float2(v0, v1);
            *(float2*)(C + (size_t)(r0 + 8) * ldc + c0) = make_float2(v2, v3);
        }
}

// Kernel 1: fused QKV projection; V output rounded to tf32 (PV exactness)
__global__ void __launch_bounds__(256, 2) k_qkv_tc()
{
    const int n0 = blockIdx.x * 128;
    const int m0 = blockIdx.y * 128;
    if (n0 < 1024)
        gemm128_bf16x3(g_hid_hi, g_hid_lo, m0, g_wq_hi, g_wq_lo, n0,
                       g_q + (size_t)m0 * 1024 + n0, 1024, false);
    else if (n0 < 1536)
        gemm128_bf16x3(g_hid_hi, g_hid_lo, m0, g_wk_hi, g_wk_lo, n0 - 1024,
                       g_k + (size_t)m0 * 512 + (n0 - 1024), 512, false);
    else
        gemm128_bf16x3(g_hid_hi, g_hid_lo, m0, g_wv_hi, g_wv_lo, n0 - 1536,
                       g_v + (size_t)m0 * 512 + (n0 - 1536), 512, true);
}

// Kernel 5: output projection from packed attention output
__global__ void __launch_bounds__(256, 2) k_out_tc(float* __restrict__ out)
{
    const int n0 = blockIdx.x * 128;
    const int m0 = blockIdx.y * 128;
    gemm128_bf16x3(g_at_hi, g_at_lo, m0, g_wo_hi, g_wo_lo, n0,
                   out + (size_t)m0 * 1024 + n0, 1024, false);
}

// ---------------------------------------------------------------------------
// Kernel 2: RoPE on K ONLY (Q rope fused into attention Q-fragment load).
// Writes tf32-RNA-rounded values (QK exactness).
// ---------------------------------------------------------------------------
__global__ void k_ropek(const float* __restrict__ cosb, const float* __restrict__ sinb)
{
    const int t = blockIdx.x * blockDim.x + threadIdx.x;
    const int total = CBS * CKV * 64;
    if (t >= total) return;
    const int d = t & 63;
    const int head = (t >> 6) & 3;
    const int row = t >> 8;
    const int s = row & (CS - 1);
    const float c1  = cosb[s * CD + d];
    const float sn1 = sinb[s * CD + d];
    const float c2  = cosb[s * CD + d + 64];
    const float sn2 = sinb[s * CD + d + 64];
    float* p = g_k + (size_t)row * (CKV * CD) + head * CD;
    const float x1 = p[d], x2 = p[d + 64];
    p[d]      = tf32r(x1 * c1 - x2 * sn1);
    p[d + 64] = tf32r(x2 * c2 + x1 * sn2);
}

// ---------------------------------------------------------------------------
// Kernel 3: dt = v_flat @ Wdt ; dyn = exp(A * softplus(dt)) -> g_biasT [h][b][s]
// ---------------------------------------------------------------------------
__global__ void __launch_bounds__(256) k_biask(
    const float* __restrict__ Wdt, const float* __restrict__ Aw)
{
    __shared__ float sW[512 * 8];
    for (int i = threadIdx.x; i < 512 * 8; i += 256) sW[i] = Wdt[i];
    __syncthreads();
    const int warp = threadIdx.x >> 5;
    const int lane = threadIdx.x & 31;
    const int row = blockIdx.x * 8 + warp;
    const float* vrow = g_v + (size_t)row * 512;
    float acc[8];
#pragma unroll
    for (int h = 0; h < 8; ++h) acc[h] = 0.f;
    for (int j = lane; j < 512; j += 32) {
        const float vv = vrow[j];
#pragma unroll
        for (int h = 0; h < 8; ++h) acc[h] = fmaf(vv, sW[j * 8 + h], acc[h]);
    }
#pragma unroll
    for (int off = 16; off > 0; off >>= 1)
#pragma unroll
        for (int h = 0; h < 8; ++h)
            acc[h] += __shfl_xor_sync(0xffffffffu, acc[h], off);
    if (lane < 8) {
        const float dt = acc[lane];
        const float sp = (dt > 20.f) ? dt : log1pf(expf(dt));
        const int b = row >> 11;
        const int s = row & (CS - 1);
        g_biasT[(size_t)(lane * CB + b) * CS + s] = expf(Aw[lane] * sp);
    }
}

// ===========================================================================
// Kernel 4: causal flash attention, tf32 mma. Round-12 256-CTA schedule
// (reversed blockIdx.y: heavy tiles first). Q RoPE fused into fragment load:
// aq[kf] (d) pairs with aq[kf+8] (d+64) thread-locally -> in-register rope,
// then tf32-RNA round. Bit-identical to the standalone rope kernel's output.
// ===========================================================================
#define KSTR 132
#define VSTR 136
#define PST 68
#define AT_KS 0
#define AT_VS (2 * 64 * KSTR)
#define AT_PS (AT_VS + 2 * 64 * VSTR)
#define AT_BIAS (AT_PS + 128 * PST)
#define ATTN_TC_FLOATS (AT_BIAS + 2 * 64)
#define ATTN_TC_BYTES (ATTN_TC_FLOATS * 4)

__global__ void __launch_bounds__(256, 1) k_attn_tc(
    const float* __restrict__ cosb, const float* __restrict__ sinb)
{
    extern __shared__ float sm[];
    float* Ks = sm + AT_KS;
    float* Vs = sm + AT_VS;
    float* Ps = sm + AT_PS;
    float* bias_s = sm + AT_BIAS;
    const unsigned smBase = (unsigned)__cvta_generic_to_shared(sm);

    const int tid = threadIdx.x;
    const int w = tid >> 5, lane = tid & 31;
    const int g = lane >> 2, t = lane & 3;
    const int bh = blockIdx.x;
    const int b = bh >> 3;
    const int h = bh & 7;
    const int kvh = h >> 1;
    const int qt = (int)gridDim.y - 1 - (int)blockIdx.y;
    const int q0 = qt * 128;
    const int qw = w * 16;
    const int qg0 = q0 + qw + g;
    const int qg1 = qg0 + 8;

    // Q fragments: load raw fp32 q, apply RoPE in-register, round to tf32.
    unsigned aq[16][4];
    {
        const float* qp = g_q + (size_t)(b * CS + qg0) * 1024 + h * 128;
#pragma unroll
        for (int kf = 0; kf < 16; ++kf) {
            aq[kf][0] = __float_as_uint(qp[kf * 8 + t]);
            aq[kf][1] = __float_as_uint(qp[8 * 1024 + kf * 8 + t]);
            aq[kf][2] = __float_as_uint(qp[kf * 8 + t + 4]);
            aq[kf][3] = __float_as_uint(qp[8 * 1024 + kf * 8 + t + 4]);
        }
#pragma unroll
        for (int kf = 0; kf < 8; ++kf) {
#pragma unroll
            for (int r = 0; r < 4; ++r) {
                const int d = kf * 8 + t + ((r >= 2) ? 4 : 0);
                const int s = (r & 1) ? qg1 : qg0;
                const float c1  = cosb[s * CD + d];
                const float sn1 = sinb[s * CD + d];
                const float c2  = cosb[s * CD + d + 64];
                const float sn2 = sinb[s * CD + d + 64];
                const float x1 = __uint_as_float(aq[kf][r]);
                const float x2 = __uint_as_float(aq[kf + 8][r]);
                aq[kf][r]     = f2tf32(x1 * c1 - x2 * sn1);
                aq[kf + 8][r] = f2tf32(x2 * c2 + x1 * sn2);
            }
        }
    }

    float O[16][4];
#pragma unroll
    for (int nt = 0; nt < 16; ++nt)
#pragma unroll
        for (int r = 0; r < 4; ++r) O[nt][r] = 0.f;
    float m0 = -1e30f, m1 = -1e30f, l0 = 0.f, l1 = 0.f;

    const int nkt = 2 * qt + 2;

    auto issue = [&](int kt, int st) {
        const int kbase = kt * 64;
#pragma unroll
        for (int i = 0; i < 8; ++i) {
            const int idx = tid + i * 256;
            const int c = idx >> 5, dc = (idx & 31) << 2;
            const size_t grow = (size_t)(b * CS + kbase + c) * 512 + kvh * 128 + dc;
            cp16(smBase + (unsigned)((AT_KS + st * 64 * KSTR + c * KSTR + dc) << 2), g_k + grow);
            cp16(smBase + (unsigned)((AT_VS + st * 64 * VSTR + c * VSTR + dc) << 2), g_v + grow);
        }
        if (tid < 16)
            cp16(smBase + (unsigned)((AT_BIAS + st * 64 + tid * 4) << 2),
                 g_biasT + (size_t)(h * CB + b) * CS + kbase + tid * 4);
        asm volatile("cp.async.commit_group;\n");
    };

    issue(0, 0);
    int st = 0;
    for (int kt = 0; kt < nkt; ++kt) {
        const int kbase = kt * 64;
        asm volatile("cp.async.wait_group 0;\n");
        __syncthreads();
        if (kt + 1 < nkt) issue(kt + 1, st ^ 1);

        const float* KsS = Ks + st * 64 * KSTR;
        const float* VsS = Vs + st * 64 * VSTR;
        const float* biasS = bias_s + st * 64;

        float sacc[8][4];
#pragma unroll
        for (int nt = 0; nt < 8; ++nt)
#pragma unroll
            for (int r = 0; r < 4; ++r) sacc[nt][r] = 0.f;
#pragma unroll
        for (int kf = 0; kf < 16; ++kf) {
#pragma unroll
            for (int nt = 0; nt < 8; ++nt) {
                unsigned bf[2];
                const float* kp = KsS + (nt * 8 + g) * KSTR + kf * 8 + t;
                bf[0] = __float_as_uint(kp[0]);
                bf[1] = __float_as_uint(kp[4]);
                mma_tf32(sacc[nt], aq[kf], bf);
            }
        }

        float mx0 = -1e30f, mx1 = -1e30f;
#pragma unroll
        for (int nt = 0; nt < 8; ++nt) {
            const int kg = kbase + nt * 8 + 2 * t;
            const float b0 = biasS[nt * 8 + 2 * t];
            const float b1 = biasS[nt * 8 + 2 * t + 1];
            sacc[nt][0] = (kg     <= qg0) ? fmaf(sacc[nt][0], CSCALE, b0) : -1e30f;
            sacc[nt][1] = (kg + 1 <= qg0) ? fmaf(sacc[nt][1], CSCALE, b1) : -1e30f;
            sacc[nt][2] = (kg     <= qg1) ? fmaf(sacc[nt][2], CSCALE, b0) : -1e30f;
            sacc[nt][3] = (kg + 1 <= qg1) ? fmaf(sacc[nt][3], CSCALE, b1) : -1e30f;
            mx0 = fmaxf(mx0, fmaxf(sacc[nt][0], sacc[nt][1]));
            mx1 = fmaxf(mx1, fmaxf(sacc[nt][2], sacc[nt][3]));
        }
        mx0 = fmaxf(mx0, __shfl_xor_sync(0xffffffffu, mx0, 1));
        mx0 = fmaxf(mx0, __shfl_xor_sync(0xffffffffu, mx0, 2));
        mx1 = fmaxf(mx1, __shfl_xor_sync(0xffffffffu, mx1, 1));
        mx1 = fmaxf(mx1, __shfl_xor_sync(0xffffffffu, mx1, 2));

        const float mn0 = fmaxf(m0, mx0);
        const float mn1 = fmaxf(m1, mx1);
        const float alpha0 = __expf(m0 - mn0);
        const float alpha1 = __expf(m1 - mn1);
        float sum0 = 0.f, sum1 = 0.f;
#pragma unroll
        for (int nt = 0; nt < 8; ++nt) {
            const float p0 = tf32r(__expf(sacc[nt][0] - mn0));
            const float p1 = tf32r(__expf(sacc[nt][1] - mn0));
            const float p2 = tf32r(__expf(sacc[nt][2] - mn1));
            const float p3 = tf32r(__expf(sacc[nt][3] - mn1));
            sum0 += p0 + p1;
            sum1 += p2 + p3;
            *(float2*)&Ps[(qw + g) * PST + nt * 8 + 2 * t]     = make_float2(p0, p1);
            *(float2*)&Ps[(qw + g + 8) * PST + nt * 8 + 2 * t] = make_float2(p2, p3);
        }
        sum0 += __shfl_xor_sync(0xffffffffu, sum0, 1);
        sum0 += __shfl_xor_sync(0xffffffffu, sum0, 2);
        sum1 += __shfl_xor_sync(0xffffffffu, sum1, 1);
        sum1 += __shfl_xor_sync(0xffffffffu, sum1, 2);
        l0 = l0 * alpha0 + sum0;  m0 = mn0;
        l1 = l1 * alpha1 + sum1;  m1 = mn1;

#pragma unroll
        for (int nt = 0; nt < 16; ++nt) {
            O[nt][0] *= alpha0; O[nt][1] *= alpha0;
            O[nt][2] *= alpha1; O[nt][3] *= alpha1;
        }

        __syncwarp();
#pragma unroll
        for (int kf = 0; kf < 8; ++kf) {
            unsigned ap[4];
            const float* pp = Ps + (qw + g) * PST + kf * 8 + t;
            ap[0] = __float_as_uint(pp[0]);
            ap[1] = __float_as_uint(pp[8 * PST]);
            ap[2] = __float_as_uint(pp[4]);
            ap[3] = __float_as_uint(pp[8 * PST + 4]);
#pragma unroll
            for (int nt = 0; nt < 16; ++nt) {
                unsigned bf[2];
                const float* vp = VsS + (kf * 8 + t) * VSTR + nt * 8 + g;
                bf[0] = __float_as_uint(vp[0]);
                bf[1] = __float_as_uint(vp[4 * VSTR]);
                mma_tf32(O[nt], ap, bf);
            }
        }
        __syncthreads();
        st ^= 1;
    }

    // epilogue: normalize and pack to bf16x3 operand layout for k_out.
    const float inv0 = 1.f / l0;
    const float inv1 = 1.f / l1;
    const size_t r0 = (size_t)(b * CS + qg0) * 512 + h * 64;
    const size_t r1 = (size_t)(b * CS + qg1) * 512 + h * 64;
#pragma unroll
    for (int nt = 0; nt < 16; ++nt) {
        unsigned hi, lo;
        bf16x3_pack(O[nt][0] * inv0, O[nt][1] * inv0, hi, lo);
        g_at_hi[r0 + nt * 4 + t] = hi;
        g_at_lo[r0 + nt * 4 + t] = lo;
        bf16x3_pack(O[nt][2] * inv1, O[nt][3] * inv1, hi, lo);
        g_at_hi[r1 + nt * 4 + t] = hi;
        g_at_lo[r1 + nt * 4 + t] = lo;
    }
}

// ---------------------------------------------------------------------------
extern "C" void kernel_launch(void* const* d_in, const int* in_sizes, int n_in,
                              void* d_out, int out_size)
{
    const float* hidden = (const float*)d_in[0];
    const float* Wq     = (const float*)d_in[1];
    const float* Wk     = (const float*)d_in[2];
    const float* Wv     = (const float*)d_in[3];
    const float* Wdt    = (const float*)d_in[4];
    const float* Aw     = (const float*)d_in[5];
    const float* Wo     = (const float*)d_in[6];
    const float* cosb   = (const float*)d_in[7];
    const float* sinb   = (const float*)d_in[8];
    float* out = (float*)d_out;

    cudaFuncSetAttribute(k_qkv_tc,  cudaFuncAttributeMaxDynamicSharedMemorySize, GEMM_SMEM_BYTES);
    cudaFuncSetAttribute(k_out_tc,  cudaFuncAttributeMaxDynamicSharedMemorySize, GEMM_SMEM_BYTES);
    cudaFuncSetAttribute(k_attn_tc, cudaFuncAttributeMaxDynamicSharedMemorySize, ATTN_TC_BYTES);

    // one-time packs (destinations resolved inside device code)
    k_cvtA<<<(CBS * 512 + 255) / 256, 256>>>(hidden);
    k_cvtW_all<<<dim3(16, 32, 4), 256>>>(Wq, Wk, Wv, Wo);

    k_qkv_tc<<<dim3(16, 32), 256, GEMM_SMEM_BYTES>>>();
    k_ropek<<<(CBS * CKV * 64 + 255) / 256, 256>>>(cosb, sinb);
    k_biask<<<CBS / 8, 256>>>(Wdt, Aw);
    k_attn_tc<<<dim3(16, 16), 256, ATTN_TC_BYTES>>>(cosb, sinb);
    k_out_tc<<<dim3(8, 32), 256, GEMM_SMEM_BYTES>>>(out);
}

// round 16
// speedup vs baseline: 1.1515x; 1.1098x over previous
#include <cuda_runtime.h>
#include <cuda_bf16.h>
#include <math.h>

// Problem constants
#define CB 2
#define CS 2048
#define CHID 1024
#define CH 8
#define CKV 4
#define CD 128
#define CBS (CB * CS)                 // 4096 rows
#define CSCALE 0.08838834764831845f   // 128^-0.5

// Scratch (allocation-free rule: __device__ globals)
__device__ float g_q[CBS * CH * CD];      // raw fp32 (rope+round fused into attn)
__device__ float g_k[CBS * CKV * CD];     // raw fp32 (ropek ropes+rounds)
__device__ float g_v[CBS * CKV * CD];     // tf32-RNA rounded at qkv epilogue
__device__ float g_biasT[CH * CB * CS];   // dyn transposed: [h][b][s]

// bf16x3 packed operands for the OUTPUT projection only
__device__ unsigned g_wo_hi[1024 * 512], g_wo_lo[1024 * 512];   // [col][k2]
__device__ unsigned g_at_hi[CBS * 512],  g_at_lo[CBS * 512];    // attn out packed

__device__ __forceinline__ void cp16(unsigned dst, const void* src) {
    asm volatile("cp.async.cg.shared.global [%0], [%1], 16;\n" :: "r"(dst), "l"(src));
}

__device__ __forceinline__ unsigned f2tf32(float x) {
    unsigned r;
    asm("cvt.rna.tf32.f32 %0, %1;\n" : "=r"(r) : "f"(x));
    return r;
}
__device__ __forceinline__ float tf32r(float x) { return __uint_as_float(f2tf32(x)); }

__device__ __forceinline__ void mma_tf32(float* d, const unsigned* a, const unsigned* b) {
    asm volatile(
        "mma.sync.aligned.m16n8k8.row.col.f32.tf32.tf32.f32 "
        "{%0,%1,%2,%3}, {%4,%5,%6,%7}, {%8,%9}, {%0,%1,%2,%3};\n"
        : "+f"(d[0]), "+f"(d[1]), "+f"(d[2]), "+f"(d[3])
        : "r"(a[0]), "r"(a[1]), "r"(a[2]), "r"(a[3]), "r"(b[0]), "r"(b[1]));
}

__device__ __forceinline__ void mma_bf16(float* d, const unsigned* a, const unsigned* b) {
    asm volatile(
        "mma.sync.aligned.m16n8k16.row.col.f32.bf16.bf16.f32 "
        "{%0,%1,%2,%3}, {%4,%5,%6,%7}, {%8,%9}, {%0,%1,%2,%3};\n"
        : "+f"(d[0]), "+f"(d[1]), "+f"(d[2]), "+f"(d[3])
        : "r"(a[0]), "r"(a[1]), "r"(a[2]), "r"(a[3]), "r"(b[0]), "r"(b[1]));
}

// pack pair (x0 -> low16, x1 -> high16) into hi/lo bf16 residual split
__device__ __forceinline__ void bf16x3_pack(float x0, float x1, unsigned& hi, unsigned& lo) {
    const __nv_bfloat16 h0 = __float2bfloat16_rn(x0);
    const __nv_bfloat16 h1 = __float2bfloat16_rn(x1);
    const __nv_bfloat16 l0 = __float2bfloat16_rn(x0 - __bfloat162float(h0));
    const __nv_bfloat16 l1 = __float2bfloat16_rn(x1 - __bfloat162float(h1));
    __nv_bfloat162 H; H.x = h0; H.y = h1;
    __nv_bfloat162 L; L.x = l0; L.y = l1;
    hi = *(const unsigned*)&H;
    lo = *(const unsigned*)&L;
}

// ---------------------------------------------------------------------------
// Convert kernel: Wo -> transposed packed bf16 pairs (device-resolved dest)
// ---------------------------------------------------------------------------
__global__ void __launch_bounds__(256) k_cvtWo(const float* __restrict__ src)
{
    __shared__ float smW[64][33];
    const int tid = threadIdx.x;
    const int k0 = blockIdx.x * 64;
    const int n0 = blockIdx.y * 32;
#pragma unroll
    for (int i = 0; i < 8; ++i) {
        const int idx = tid + i * 256;
        const int r = idx >> 5, c = idx & 31;
        smW[r][c] = src[(size_t)(k0 + r) * 1024 + n0 + c];
    }
    __syncthreads();
    const int n = tid >> 3;
#pragma unroll
    for (int j = 0; j < 4; ++j) {
        const int k2 = (tid & 7) + j * 8;
        unsigned hi, lo;
        bf16x3_pack(smW[2 * k2][n], smW[2 * k2 + 1][n], hi, lo);
        const size_t o = (size_t)(n0 + n) * 512 + (k0 >> 1) + k2;
        g_wo_hi[o] = hi; g_wo_lo[o] = lo;
    }
}

// ===========================================================================
// SINGLE-PASS tf32 GEMM for QKV: C[128,128] = A[128,1024] @ B[1024,128].
// Raw fp32 staged; operands RNA-rounded to tf32 in-register after LDS (free:
// ALU is not the binder); ONE m16n8k8 mma per k8 -> 2 instr/k16 vs bf16x3's 3.
// Exact over rounded inputs. A pad 36, B pad 132 (conflict-free frags).
// ===========================================================================
#define QAS_OFF 0
#define QBS_OFF (2 * 4608)                       // 9216
#define QKV_SMEM_FLOATS (QBS_OFF + 2 * 4224)     // 17664
#define QKV_SMEM_BYTES (QKV_SMEM_FLOATS * 4)     // 70656

__device__ __forceinline__ void gemm128_tf32_1p(
    const float* __restrict__ A, int lda,
    const float* __restrict__ B, int ldb,
    float* __restrict__ C, int ldc, bool roundC)
{
    extern __shared__ float smf[];
    const unsigned smBase = (unsigned)__cvta_generic_to_shared(smf);

    const int tid = threadIdx.x;
    const int w = tid >> 5, lane = tid & 31;
    const int g = lane >> 2, t = lane & 3;
    const int rb = (w >> 2) * 64;
    const int cb = (w & 3) * 32;

    float acc[4][4][4];
#pragma unroll
    for (int mt = 0; mt < 4; ++mt)
#pragma unroll
        for (int nt = 0; nt < 4; ++nt)
#pragma unroll
            for (int r = 0; r < 4; ++r) acc[mt][nt][r] = 0.f;

    auto issue = [&](int k0, int s) {
#pragma unroll
        for (int i = 0; i < 4; ++i) {
            const int idx = tid + i * 256;
            const int r = idx >> 3, c = (idx & 7) << 2;
            cp16(smBase + (unsigned)((QAS_OFF + s * 4608 + r * 36 + c) << 2),
                 A + (size_t)r * lda + k0 + c);
        }
#pragma unroll
        for (int i = 0; i < 4; ++i) {
            const int idx = tid + i * 256;
            const int r = idx >> 5, c = (idx & 31) << 2;
            cp16(smBase + (unsigned)((QBS_OFF + s * 4224 + r * 132 + c) << 2),
                 B + (size_t)(k0 + r) * ldb + c);
        }
        asm volatile("cp.async.commit_group;\n");
    };

    issue(0, 0);
    int s = 0;
    for (int k0 = 0; k0 < 1024; k0 += 32) {
        asm volatile("cp.async.wait_group 0;\n");
        __syncthreads();
        if (k0 + 32 < 1024) issue(k0 + 32, s ^ 1);
        const float* AsS = smf + QAS_OFF + s * 4608;
        const float* BsS = smf + QBS_OFF + s * 4224;
#pragma unroll
        for (int ks = 0; ks < 4; ++ks) {
            const int kk = ks * 8;
            unsigned af[4][4], bf[4][2];
#pragma unroll
            for (int mt = 0; mt < 4; ++mt) {
                const float* p = AsS + (rb + mt * 16 + g) * 36 + kk + t;
                af[mt][0] = f2tf32(p[0]);
                af[mt][1] = f2tf32(p[8 * 36]);
                af[mt][2] = f2tf32(p[4]);
                af[mt][3] = f2tf32(p[8 * 36 + 4]);
            }
#pragma unroll
            for (int nt = 0; nt < 4; ++nt) {
                const float* p = BsS + (kk + t) * 132 + cb + nt * 8 + g;
                bf[nt][0] = f2tf32(p[0]);
                bf[nt][1] = f2tf32(p[4 * 132]);
            }
#pragma unroll
            for (int mt = 0; mt < 4; ++mt)
#pragma unroll
                for (int nt = 0; nt < 4; ++nt)
                    mma_tf32(acc[mt][nt], af[mt], bf[nt]);
        }
        s ^= 1;
    }

#pragma unroll
    for (int mt = 0; mt < 4; ++mt)
#pragma unroll
        for (int nt = 0; nt < 4; ++nt) {
            const int r0 = rb + mt * 16 + g;
            const int c0 = cb + nt * 8 + 2 * t;
            float v0 = acc[mt][nt][0], v1 = acc[mt][nt][1];
            float v2 = acc[mt][nt][2], v3 = acc[mt][nt][3];
            if (roundC) { v0 = tf32r(v0); v1 = tf32r(v1); v2 = tf32r(v2); v3 = tf32r(v3); }
            *(float2*)(C + (size_t)r0 * ldc + c0)       = make_float2(v0, v1);
            *(float2*)(C + (size_t)(r0 + 8) * ldc + c0) = make_float2(v2, v3);
        }
}

// Kernel 1: fused QKV projection, single-pass tf32; V output rounded to tf32
__global__ void __launch_bounds__(256, 2) k_qkv_tc(
    const float* __restrict__ hidden,
    const float* __restrict__ Wq,
    const float* __restrict__ Wk,
    const float* __restrict__ Wv)
{
    const int n0 = blockIdx.x * 128;
    const int m0 = blockIdx.y * 128;
    const float* A = hidden + (size_t)m0 * CHID;
    if (n0 < 1024)
        gemm128_tf32_1p(A, CHID, Wq + n0, 1024, g_q + (size_t)m0 * 1024 + n0, 1024, false);
    else if (n0 < 1536)
        gemm128_tf32_1p(A, CHID, Wk + (n0 - 1024), 512, g_k + (size_t)m0 * 512 + (n0 - 1024), 512, false);
    else
        gemm128_tf32_1p(A, CHID, Wv + (n0 - 1536), 512, g_v + (size_t)m0 * 512 + (n0 - 1536), 512, true);
}

// ===========================================================================
// bf16x3 GEMM for the OUTPUT projection (protects final precision)
// ===========================================================================
#define PSTRIDE 20
#define STG_U32 (128 * PSTRIDE)       // 2560 per array per stage
#define SA_H 0
#define SA_L (2 * STG_U32)            // 5120
#define SB_H (4 * STG_U32)            // 10240
#define SB_L (6 * STG_U32)            // 15360
#define GEMM_SMEM_BYTES (8 * STG_U32 * 4)   // 81920

__global__ void __launch_bounds__(256, 2) k_out_tc(float* __restrict__ out)
{
    const int n0 = blockIdx.x * 128;
    const int m0 = blockIdx.y * 128;
    float* C = out + (size_t)m0 * 1024 + n0;

    extern __shared__ unsigned smu[];
    const unsigned smBase = (unsigned)__cvta_generic_to_shared(smu);

    const int tid = threadIdx.x;
    const int w = tid >> 5, lane = tid & 31;
    const int g = lane >> 2, t = lane & 3;
    const int rb = (w >> 2) * 64;
    const int cb = (w & 3) * 32;

    float acc[4][4][4];
#pragma unroll
    for (int mt = 0; mt < 4; ++mt)
#pragma unroll
        for (int nt = 0; nt < 4; ++nt)
#pragma unroll
            for (int r = 0; r < 4; ++r) acc[mt][nt][r] = 0.f;

    const unsigned* srcs[4] = { g_at_hi, g_at_lo, g_wo_hi, g_wo_lo };
    const int base0[4] = { m0, m0, n0, n0 };
    const int dstb[4] = { SA_H, SA_L, SB_H, SB_L };

    auto issue = [&](int k0, int st) {
        const int k2_0 = k0 >> 1;
#pragma unroll
        for (int i = 0; i < 8; ++i) {
            const int idx = tid + i * 256;
            const int sub = idx >> 9;
            const int j = idx & 511;
            const int r = j >> 2, c4 = (j & 3) << 2;
            cp16(smBase + (unsigned)((dstb[sub] + st * STG_U32 + r * PSTRIDE + c4) << 2),
                 srcs[sub] + (size_t)(base0[sub] + r) * 512 + k2_0 + c4);
        }
        asm volatile("cp.async.commit_group;\n");
    };

    issue(0, 0);
    int st = 0;
    for (int k0 = 0; k0 < 1024; k0 += 32) {
        asm volatile("cp.async.wait_group 0;\n");
        __syncthreads();
        if (k0 + 32 < 1024) issue(k0 + 32, st ^ 1);
        const unsigned* AH = smu + SA_H + st * STG_U32;
        const unsigned* AL = smu + SA_L + st * STG_U32;
        const unsigned* BH = smu + SB_H + st * STG_U32;
        const unsigned* BL = smu + SB_L + st * STG_U32;
#pragma unroll
        for (int ks = 0; ks < 2; ++ks) {
            const int kk2 = ks * 8;
            unsigned ah[4][4], al[4][4], bh[4][2], bl[4][2];
#pragma unroll
            for (int mt = 0; mt < 4; ++mt) {
                const int ro = (rb + mt * 16 + g) * PSTRIDE + kk2;
                ah[mt][0] = AH[ro + t];
                ah[mt][1] = AH[ro + 8 * PSTRIDE + t];
                ah[mt][2] = AH[ro + t + 4];
                ah[mt][3] = AH[ro + 8 * PSTRIDE + t + 4];
                al[mt][0] = AL[ro + t];
                al[mt][1] = AL[ro + 8 * PSTRIDE + t];
                al[mt][2] = AL[ro + t + 4];
                al[mt][3] = AL[ro + 8 * PSTRIDE + t + 4];
            }
#pragma unroll
            for (int nt = 0; nt < 4; ++nt) {
                const int co = (cb + nt * 8 + g) * PSTRIDE + kk2;
                bh[nt][0] = BH[co + t];
                bh[nt][1] = BH[co + t + 4];
                bl[nt][0] = BL[co + t];
                bl[nt][1] = BL[co + t + 4];
            }
#pragma unroll
            for (int mt = 0; mt < 4; ++mt)
#pragma unroll
                for (int nt = 0; nt < 4; ++nt) {
                    mma_bf16(acc[mt][nt], al[mt], bh[nt]);
                    mma_bf16(acc[mt][nt], ah[mt], bl[nt]);
                    mma_bf16(acc[mt][nt], ah[mt], bh[nt]);
                }
        }
        st ^= 1;
    }

#pragma unroll
    for (int mt = 0; mt < 4; ++mt)
#pragma unroll
        for (int nt = 0; nt < 4; ++nt) {
            const int r0 = rb + mt * 16 + g;
            const int c0 = cb + nt * 8 + 2 * t;
            *(float2*)(C + (size_t)r0 * 1024 + c0) =
                make_float2(acc[mt][nt][0], acc[mt][nt][1]);
            *(float2*)(C + (size_t)(r0 + 8) * 1024 + c0) =
                make_float2(acc[mt][nt][2], acc[mt][nt][3]);
        }
}

// ---------------------------------------------------------------------------
// Kernel 2: RoPE on K ONLY; writes tf32-RNA-rounded values (QK exactness)
// ---------------------------------------------------------------------------
__global__ void k_ropek(const float* __restrict__ cosb, const float* __restrict__ sinb)
{
    const int t = blockIdx.x * blockDim.x + threadIdx.x;
    const int total = CBS * CKV * 64;
    if (t >= total) return;
    const int d = t & 63;
    const int head = (t >> 6) & 3;
    const int row = t >> 8;
    const int s = row & (CS - 1);
    const float c1  = cosb[s * CD + d];
    const float sn1 = sinb[s * CD + d];
    const float c2  = cosb[s * CD + d + 64];
    const float sn2 = sinb[s * CD + d + 64];
    float* p = g_k + (size_t)row * (CKV * CD) + head * CD;
    const float x1 = p[d], x2 = p[d + 64];
    p[d]      = tf32r(x1 * c1 - x2 * sn1);
    p[d + 64] = tf32r(x2 * c2 + x1 * sn2);
}

// ---------------------------------------------------------------------------
// Kernel 3: dt = v_flat @ Wdt ; dyn = exp(A * softplus(dt)) -> g_biasT [h][b][s]
// ---------------------------------------------------------------------------
__global__ void __launch_bounds__(256) k_biask(
    const float* __restrict__ Wdt, const float* __restrict__ Aw)
{
    __shared__ float sW[512 * 8];
    for (int i = threadIdx.x; i < 512 * 8; i += 256) sW[i] = Wdt[i];
    __syncthreads();
    const int warp = threadIdx.x >> 5;
    const int lane = threadIdx.x & 31;
    const int row = blockIdx.x * 8 + warp;
    const float* vrow = g_v + (size_t)row * 512;
    float acc[8];
#pragma unroll
    for (int h = 0; h < 8; ++h) acc[h] = 0.f;
    for (int j = lane; j < 512; j += 32) {
        const float vv = vrow[j];
#pragma unroll
        for (int h = 0; h < 8; ++h) acc[h] = fmaf(vv, sW[j * 8 + h], acc[h]);
    }
#pragma unroll
    for (int off = 16; off > 0; off >>= 1)
#pragma unroll
        for (int h = 0; h < 8; ++h)
            acc[h] += __shfl_xor_sync(0xffffffffu, acc[h], off);
    if (lane < 8) {
        const float dt = acc[lane];
        const float sp = (dt > 20.f) ? dt : log1pf(expf(dt));
        const int b = row >> 11;
        const int s = row & (CS - 1);
        g_biasT[(size_t)(lane * CB + b) * CS + s] = expf(Aw[lane] * sp);
    }
}

// ===========================================================================
// Kernel 4: causal flash attention, tf32 mma (round-14 version; Q rope fused)
// ===========================================================================
#define KSTR 132
#define VSTR 136
#define PST 68
#define AT_KS 0
#define AT_VS (2 * 64 * KSTR)
#define AT_PS (AT_VS + 2 * 64 * VSTR)
#define AT_BIAS (AT_PS + 128 * PST)
#define ATTN_TC_FLOATS (AT_BIAS + 2 * 64)
#define ATTN_TC_BYTES (ATTN_TC_FLOATS * 4)

__global__ void __launch_bounds__(256, 1) k_attn_tc(
    const float* __restrict__ cosb, const float* __restrict__ sinb)
{
    extern __shared__ float sm[];
    float* Ks = sm + AT_KS;
    float* Vs = sm + AT_VS;
    float* Ps = sm + AT_PS;
    float* bias_s = sm + AT_BIAS;
    const unsigned smBase = (unsigned)__cvta_generic_to_shared(sm);

    const int tid = threadIdx.x;
    const int w = tid >> 5, lane = tid & 31;
    const int g = lane >> 2, t = lane & 3;
    const int bh = blockIdx.x;
    const int b = bh >> 3;
    const int h = bh & 7;
    const int kvh = h >> 1;
    const int qt = (int)gridDim.y - 1 - (int)blockIdx.y;
    const int q0 = qt * 128;
    const int qw = w * 16;
    const int qg0 = q0 + qw + g;
    const int qg1 = qg0 + 8;

    // Q fragments: load raw fp32 q, apply RoPE in-register, round to tf32.
    unsigned aq[16][4];
    {
        const float* qp = g_q + (size_t)(b * CS + qg0) * 1024 + h * 128;
#pragma unroll
        for (int kf = 0; kf < 16; ++kf) {
            aq[kf][0] = __float_as_uint(qp[kf * 8 + t]);
            aq[kf][1] = __float_as_uint(qp[8 * 1024 + kf * 8 + t]);
            aq[kf][2] = __float_as_uint(qp[kf * 8 + t + 4]);
            aq[kf][3] = __float_as_uint(qp[8 * 1024 + kf * 8 + t + 4]);
        }
#pragma unroll
        for (int kf = 0; kf < 8; ++kf) {
#pragma unroll
            for (int r = 0; r < 4; ++r) {
                const int d = kf * 8 + t + ((r >= 2) ? 4 : 0);
                const int s = (r & 1) ? qg1 : qg0;
                const float c1  = cosb[s * CD + d];
                const float sn1 = sinb[s * CD + d];
                const float c2  = cosb[s * CD + d + 64];
                const float sn2 = sinb[s * CD + d + 64];
                const float x1 = __uint_as_float(aq[kf][r]);
                const float x2 = __uint_as_float(aq[kf + 8][r]);
                aq[kf][r]     = f2tf32(x1 * c1 - x2 * sn1);
                aq[kf + 8][r] = f2tf32(x2 * c2 + x1 * sn2);
            }
        }
    }

    float O[16][4];
#pragma unroll
    for (int nt = 0; nt < 16; ++nt)
#pragma unroll
        for (int r = 0; r < 4; ++r) O[nt][r] = 0.f;
    float m0 = -1e30f, m1 = -1e30f, l0 = 0.f, l1 = 0.f;

    const int nkt = 2 * qt + 2;

    auto issue = [&](int kt, int st) {
        const int kbase = kt * 64;
#pragma unroll
        for (int i = 0; i < 8; ++i) {
            const int idx = tid + i * 256;
            const int c = idx >> 5, dc = (idx & 31) << 2;
            const size_t grow = (size_t)(b * CS + kbase + c) * 512 + kvh * 128 + dc;
            cp16(smBase + (unsigned)((AT_KS + st * 64 * KSTR + c * KSTR + dc) << 2), g_k + grow);
            cp16(smBase + (unsigned)((AT_VS + st * 64 * VSTR + c * VSTR + dc) << 2), g_v + grow);
        }
        if (tid < 16)
            cp16(smBase + (unsigned)((AT_BIAS + st * 64 + tid * 4) << 2),
                 g_biasT + (size_t)(h * CB + b) * CS + kbase + tid * 4);
        asm volatile("cp.async.commit_group;\n");
    };

    issue(0, 0);
    int st = 0;
    for (int kt = 0; kt < nkt; ++kt) {
        const int kbase = kt * 64;
        asm volatile("cp.async.wait_group 0;\n");
        __syncthreads();
        if (kt + 1 < nkt) issue(kt + 1, st ^ 1);

        const float* KsS = Ks + st * 64 * KSTR;
        const float* VsS = Vs + st * 64 * VSTR;
        const float* biasS = bias_s + st * 64;

        float sacc[8][4];
#pragma unroll
        for (int nt = 0; nt < 8; ++nt)
#pragma unroll
            for (int r = 0; r < 4; ++r) sacc[nt][r] = 0.f;
#pragma unroll
        for (int kf = 0; kf < 16; ++kf) {
#pragma unroll
            for (int nt = 0; nt < 8; ++nt) {
                unsigned bf[2];
                const float* kp = KsS + (nt * 8 + g) * KSTR + kf * 8 + t;
                bf[0] = __float_as_uint(kp[0]);
                bf[1] = __float_as_uint(kp[4]);
                mma_tf32(sacc[nt], aq[kf], bf);
            }
        }

        float mx0 = -1e30f, mx1 = -1e30f;
#pragma unroll
        for (int nt = 0; nt < 8; ++nt) {
            const int kg = kbase + nt * 8 + 2 * t;
            const float b0 = biasS[nt * 8 + 2 * t];
            const float b1 = biasS[nt * 8 + 2 * t + 1];
            sacc[nt][0] = (kg     <= qg0) ? fmaf(sacc[nt][0], CSCALE, b0) : -1e30f;
            sacc[nt][1] = (kg + 1 <= qg0) ? fmaf(sacc[nt][1], CSCALE, b1) : -1e30f;
            sacc[nt][2] = (kg     <= qg1) ? fmaf(sacc[nt][2], CSCALE, b0) : -1e30f;
            sacc[nt][3] = (kg + 1 <= qg1) ? fmaf(sacc[nt][3], CSCALE, b1) : -1e30f;
            mx0 = fmaxf(mx0, fmaxf(sacc[nt][0], sacc[nt][1]));
            mx1 = fmaxf(mx1, fmaxf(sacc[nt][2], sacc[nt][3]));
        }
        mx0 = fmaxf(mx0, __shfl_xor_sync(0xffffffffu, mx0, 1));
        mx0 = fmaxf(mx0, __shfl_xor_sync(0xffffffffu, mx0, 2));
        mx1 = fmaxf(mx1, __shfl_xor_sync(0xffffffffu, mx1, 1));
        mx1 = fmaxf(mx1, __shfl_xor_sync(0xffffffffu, mx1, 2));

        const float mn0 = fmaxf(m0, mx0);
        const float mn1 = fmaxf(m1, mx1);
        const float alpha0 = __expf(m0 - mn0);
        const float alpha1 = __expf(m1 - mn1);
        float sum0 = 0.f, sum1 = 0.f;
#pragma unroll
        for (int nt = 0; nt < 8; ++nt) {
            const float p0 = tf32r(__expf(sacc[nt][0] - mn0));
            const float p1 = tf32r(__expf(sacc[nt][1] - mn0));
            const float p2 = tf32r(__expf(sacc[nt][2] - mn1));
            const float p3 = tf32r(__expf(sacc[nt][3] - mn1));
            sum0 += p0 + p1;
            sum1 += p2 + p3;
            *(float2*)&Ps[(qw + g) * PST + nt * 8 + 2 * t]     = make_float2(p0, p1);
            *(float2*)&Ps[(qw + g + 8) * PST + nt * 8 + 2 * t] = make_float2(p2, p3);
        }
        sum0 += __shfl_xor_sync(0xffffffffu, sum0, 1);
        sum0 += __shfl_xor_sync(0xffffffffu, sum0, 2);
        sum1 += __shfl_xor_sync(0xffffffffu, sum1, 1);
        sum1 += __shfl_xor_sync(0xffffffffu, sum1, 2);
        l0 = l0 * alpha0 + sum0;  m0 = mn0;
        l1 = l1 * alpha1 + sum1;  m1 = mn1;

#pragma unroll
        for (int nt = 0; nt < 16; ++nt) {
            O[nt][0] *= alpha0; O[nt][1] *= alpha0;
            O[nt][2] *= alpha1; O[nt][3] *= alpha1;
        }

        __syncwarp();
#pragma unroll
        for (int kf = 0; kf < 8; ++kf) {
            unsigned ap[4];
            const float* pp = Ps + (qw + g) * PST + kf * 8 + t;
            ap[0] = __float_as_uint(pp[0]);
            ap[1] = __float_as_uint(pp[8 * PST]);
            ap[2] = __float_as_uint(pp[4]);
            ap[3] = __float_as_uint(pp[8 * PST + 4]);
#pragma unroll
            for (int nt = 0; nt < 16; ++nt) {
                unsigned bf[2];
                const float* vp = VsS + (kf * 8 + t) * VSTR + nt * 8 + g;
                bf[0] = __float_as_uint(vp[0]);
                bf[1] = __float_as_uint(vp[4 * VSTR]);
                mma_tf32(O[nt], ap, bf);
            }
        }
        __syncthreads();
        st ^= 1;
    }

    // epilogue: normalize and pack to bf16x3 operand layout for k_out.
    const float inv0 = 1.f / l0;
    const float inv1 = 1.f / l1;
    const size_t r0 = (size_t)(b * CS + qg0) * 512 + h * 64;
    const size_t r1 = (size_t)(b * CS + qg1) * 512 + h * 64;
#pragma unroll
    for (int nt = 0; nt < 16; ++nt) {
        unsigned hi, lo;
        bf16x3_pack(O[nt][0] * inv0, O[nt][1] * inv0, hi, lo);
        g_at_hi[r0 + nt * 4 + t] = hi;
        g_at_lo[r0 + nt * 4 + t] = lo;
        bf16x3_pack(O[nt][2] * inv1, O[nt][3] * inv1, hi, lo);
        g_at_hi[r1 + nt * 4 + t] = hi;
        g_at_lo[r1 + nt * 4 + t] = lo;
    }
}

// ---------------------------------------------------------------------------
extern "C" void kernel_launch(void* const* d_in, const int* in_sizes, int n_in,
                              void* d_out, int out_size)
{
    const float* hidden = (const float*)d_in[0];
    const float* Wq     = (const float*)d_in[1];
    const float* Wk     = (const float*)d_in[2];
    const float* Wv     = (const float*)d_in[3];
    const float* Wdt    = (const float*)d_in[4];
    const float* Aw     = (const float*)d_in[5];
    const float* Wo     = (const float*)d_in[6];
    const float* cosb   = (const float*)d_in[7];
    const float* sinb   = (const float*)d_in[8];
    float* out = (float*)d_out;

    cudaFuncSetAttribute(k_qkv_tc,  cudaFuncAttributeMaxDynamicSharedMemorySize, QKV_SMEM_BYTES);
    cudaFuncSetAttribute(k_out_tc,  cudaFuncAttributeMaxDynamicSharedMemorySize, GEMM_SMEM_BYTES);
    cudaFuncSetAttribute(k_attn_tc, cudaFuncAttributeMaxDynamicSharedMemorySize, ATTN_TC_BYTES);

    k_cvtWo<<<dim3(16, 32), 256>>>(Wo);
    k_qkv_tc<<<dim3(16, 32), 256, QKV_SMEM_BYTES>>>(hidden, Wq, Wk, Wv);
    k_ropek<<<(CBS * CKV * 64 + 255) / 256, 256>>>(cosb, sinb);
    k_biask<<<CBS / 8, 256>>>(Wdt, Aw);
    k_attn_tc<<<dim3(16, 16), 256, ATTN_TC_BYTES>>>(cosb, sinb);
    k_out_tc<<<dim3(8, 32), 256, GEMM_SMEM_BYTES>>>(out);
}